// round 2
// baseline (speedup 1.0000x reference)
#include <cuda_runtime.h>
#include <math.h>

#define NN 50000
#define NE 800000
#define INF 128
#define HID 256
#define NCLS 64

typedef unsigned long long u64;

// ---------------- device scratch (no allocation allowed) ----------------
__device__ int   g_deg[NN];
__device__ int   g_cursor[NN];
__device__ int   g_off[NN + 1];
__device__ int   g_csr[NE];
__device__ float g_invdeg[NN];
__device__ int   g_tsum[64];
__device__ float g_h0[(size_t)NN * HID];
__device__ float g_h1[(size_t)NN * HID];
__device__ float g_agg[(size_t)NN * HID];   // reused: agg0(128) / agg1(256) / t(64)+aggt(64)
__device__ float g_W2sf[HID * NCLS];
__device__ float g_W2nf[HID * NCLS];
__device__ float g_bf[NCLS];

// ---------------- CSR build ----------------
__global__ void k_zero_counts() {
    int i = blockIdx.x * blockDim.x + threadIdx.x;
    if (i < NN) { g_deg[i] = 0; g_cursor[i] = 0; }
}

__global__ void k_count(const int* __restrict__ dst) {
    int e = blockIdx.x * blockDim.x + threadIdx.x;
    if (e < NE) atomicAdd(&g_deg[dst[e]], 1);
}

// tile-wise exclusive scan (tile = 1024)
__global__ void k_scan_tiles() {
    __shared__ int sh[1024];
    int t = threadIdx.x;
    int i = blockIdx.x * 1024 + t;
    int v = (i < NN) ? g_deg[i] : 0;
    sh[t] = v;
    __syncthreads();
    for (int d = 1; d < 1024; d <<= 1) {
        int x = 0;
        if (t >= d) x = sh[t - d];
        __syncthreads();
        sh[t] += x;
        __syncthreads();
    }
    if (i < NN) g_off[i] = sh[t] - v;          // exclusive
    if (t == 1023) g_tsum[blockIdx.x] = sh[t]; // inclusive tile sum
}

__global__ void k_scan_sums(int ntiles) {
    __shared__ int sh[64];
    int t = threadIdx.x;
    int v = (t < ntiles) ? g_tsum[t] : 0;
    sh[t] = v;
    __syncthreads();
    for (int d = 1; d < 64; d <<= 1) {
        int x = 0;
        if (t >= d) x = sh[t - d];
        __syncthreads();
        sh[t] += x;
        __syncthreads();
    }
    if (t < ntiles) g_tsum[t] = sh[t] - v;     // exclusive over tile sums
}

__global__ void k_scan_fix() {
    int i = blockIdx.x * blockDim.x + threadIdx.x;
    if (i < NN) {
        g_off[i] += g_tsum[i >> 10];
        g_invdeg[i] = 1.0f / fmaxf((float)g_deg[i], 1.0f);
    }
    if (i == 0) g_off[NN] = NE;
}

__global__ void k_fill(const int* __restrict__ src, const int* __restrict__ dst) {
    int e = blockIdx.x * blockDim.x + threadIdx.x;
    if (e < NE) {
        int d = dst[e];
        int pos = g_off[d] + atomicAdd(&g_cursor[d], 1);
        g_csr[pos] = src[e];
    }
}

// ---------------- fold fc into layer 2 ----------------
__global__ void k_fuse_weights(const float* __restrict__ W2s, const float* __restrict__ W2n,
                               const float* __restrict__ b2,  const float* __restrict__ Wfc,
                               const float* __restrict__ bfc) {
    int j = blockIdx.x * blockDim.x + threadIdx.x;
    if (j < HID * NCLS) {
        int r = j / NCLS, c = j % NCLS;
        float s = 0.f, n = 0.f;
        #pragma unroll 8
        for (int k = 0; k < HID; ++k) {
            float w = Wfc[k * NCLS + c];
            s += W2s[r * HID + k] * w;
            n += W2n[r * HID + k] * w;
        }
        g_W2sf[j] = s;
        g_W2nf[j] = n;
    }
    if (j < NCLS) {
        float b = bfc[j];
        for (int k = 0; k < HID; ++k) b += b2[k] * Wfc[k * NCLS + j];
        g_bf[j] = b;
    }
}

// ---------------- mean-neighbor gather ----------------
template <int D>
__global__ void k_gather_mean(const float* __restrict__ h, float* __restrict__ agg) {
    constexpr int TPN = D / 4;  // one float4 per thread
    int gtid = blockIdx.x * blockDim.x + threadIdx.x;
    int node = gtid / TPN;
    int c    = gtid % TPN;
    if (node >= NN) return;
    int s = g_off[node], e = g_off[node + 1];
    float4 acc = make_float4(0.f, 0.f, 0.f, 0.f);
    const float4* hp = (const float4*)h;
    for (int idx = s; idx < e; ++idx) {
        int src = g_csr[idx];
        float4 v = hp[(size_t)src * TPN + c];
        acc.x += v.x; acc.y += v.y; acc.z += v.z; acc.w += v.w;
    }
    float w = g_invdeg[node];
    ((float4*)agg)[(size_t)node * TPN + c] =
        make_float4(acc.x * w, acc.y * w, acc.z * w, acc.w * w);
}

// ---------------- packed-f32x2 dual-input GEMM ----------------
// C[M x Nc] = A0 @ B0 (+ A1 @ B1) (+ bias row) (+ addend matrix)
// Each thread: 4 rows x 8 cols held as 16 packed f32x2 accumulators.
#define FMA2(acc, av, bv) \
    asm("fma.rn.f32x2 %0, %1, %2, %0;" : "+l"(acc) : "l"(av), "l"(bv))
#define PACK2(dst, s) \
    asm("mov.b64 %0, {%1, %1};" : "=l"(dst) : "f"(s))
#define UNPACK2(lo, hi, src) \
    asm("mov.b64 {%0, %1}, %2;" : "=f"(lo), "=f"(hi) : "l"(src))

template <int BM, int BN>
__global__ __launch_bounds__(256)
void k_gemm(const float* __restrict__ A0, const float* __restrict__ B0, int K0,
            const float* __restrict__ A1, const float* __restrict__ B1, int K1,
            const float* __restrict__ bias, const float* __restrict__ addend,
            float* __restrict__ C, int M, int Nc) {
    constexpr int BK = 16;
    __shared__ __align__(16) float As[BK][BM];
    __shared__ __align__(16) float Bs[BK][BN];

    const int tid = threadIdx.x;
    constexpr int TX = BN / 8;          // threads along N
    const int tx = tid % TX;            // col group (8 cols)
    const int ty = tid / TX;            // row group (4 rows)
    const int bm = blockIdx.y * BM, bn = blockIdx.x * BN;

    u64 acc[4][4] = {};                 // 4 rows x 4 col-pairs

    #pragma unroll
    for (int pair = 0; pair < 2; ++pair) {
        const float* A = pair ? A1 : A0;
        const float* B = pair ? B1 : B0;
        int K = pair ? K1 : K0;
        if (A == nullptr) continue;
        for (int k0 = 0; k0 < K; k0 += BK) {
            // load A tile (BM x BK) transposed into As[BK][BM]
            #pragma unroll
            for (int i = tid * 4; i < BM * BK; i += 1024) {
                int r = i / BK, c = i % BK;
                float4 av = make_float4(0.f, 0.f, 0.f, 0.f);
                int row = bm + r;
                if (row < M) av = *(const float4*)(A + (size_t)row * K + k0 + c);
                As[c + 0][r] = av.x;
                As[c + 1][r] = av.y;
                As[c + 2][r] = av.z;
                As[c + 3][r] = av.w;
            }
            // load B tile (BK x BN)
            #pragma unroll
            for (int i = tid * 4; i < BK * BN; i += 1024) {
                int r = i / BN, c = i % BN;
                *(float4*)&Bs[r][c] = *(const float4*)(B + (size_t)(k0 + r) * Nc + bn + c);
            }
            __syncthreads();
            #pragma unroll
            for (int k = 0; k < BK; ++k) {
                float4 a = *(const float4*)&As[k][ty * 4];
                u64 a0, a1, a2, a3;
                PACK2(a0, a.x); PACK2(a1, a.y); PACK2(a2, a.z); PACK2(a3, a.w);
                const u64* bp = (const u64*)&Bs[k][tx * 8];
                u64 b0 = bp[0], b1 = bp[1], b2 = bp[2], b3 = bp[3];
                FMA2(acc[0][0], a0, b0); FMA2(acc[0][1], a0, b1);
                FMA2(acc[0][2], a0, b2); FMA2(acc[0][3], a0, b3);
                FMA2(acc[1][0], a1, b0); FMA2(acc[1][1], a1, b1);
                FMA2(acc[1][2], a1, b2); FMA2(acc[1][3], a1, b3);
                FMA2(acc[2][0], a2, b0); FMA2(acc[2][1], a2, b1);
                FMA2(acc[2][2], a2, b2); FMA2(acc[2][3], a2, b3);
                FMA2(acc[3][0], a3, b0); FMA2(acc[3][1], a3, b1);
                FMA2(acc[3][2], a3, b2); FMA2(acc[3][3], a3, b3);
            }
            __syncthreads();
        }
    }

    // epilogue
    #pragma unroll
    for (int i = 0; i < 4; ++i) {
        int row = bm + ty * 4 + i;
        if (row >= M) continue;
        int col = bn + tx * 8;
        float r[8];
        UNPACK2(r[0], r[1], acc[i][0]);
        UNPACK2(r[2], r[3], acc[i][1]);
        UNPACK2(r[4], r[5], acc[i][2]);
        UNPACK2(r[6], r[7], acc[i][3]);
        if (bias) {
            #pragma unroll
            for (int j = 0; j < 8; ++j) r[j] += bias[col + j];
        }
        if (addend) {
            float4 d0 = *(const float4*)(addend + (size_t)row * Nc + col);
            float4 d1 = *(const float4*)(addend + (size_t)row * Nc + col + 4);
            r[0] += d0.x; r[1] += d0.y; r[2] += d0.z; r[3] += d0.w;
            r[4] += d1.x; r[5] += d1.y; r[6] += d1.z; r[7] += d1.w;
        }
        *(float4*)(C + (size_t)row * Nc + col)     = make_float4(r[0], r[1], r[2], r[3]);
        *(float4*)(C + (size_t)row * Nc + col + 4) = make_float4(r[4], r[5], r[6], r[7]);
    }
}

// ---------------- launch ----------------
extern "C" void kernel_launch(void* const* d_in, const int* in_sizes, int n_in,
                              void* d_out, int out_size) {
    const float* x    = (const float*)d_in[0];
    const int*   esrc = (const int*)d_in[1];
    const int*   edst = (const int*)d_in[2];
    const float* W0s  = (const float*)d_in[3];
    const float* W0n  = (const float*)d_in[4];
    const float* b0   = (const float*)d_in[5];
    const float* W1s  = (const float*)d_in[6];
    const float* W1n  = (const float*)d_in[7];
    const float* b1   = (const float*)d_in[8];
    const float* W2s  = (const float*)d_in[9];
    const float* W2n  = (const float*)d_in[10];
    const float* b2   = (const float*)d_in[11];
    const float* Wfc  = (const float*)d_in[12];
    const float* bfc  = (const float*)d_in[13];
    float* out = (float*)d_out;

    float *h0, *h1, *agg, *w2sf, *w2nf, *bf;
    cudaGetSymbolAddress((void**)&h0,   g_h0);
    cudaGetSymbolAddress((void**)&h1,   g_h1);
    cudaGetSymbolAddress((void**)&agg,  g_agg);
    cudaGetSymbolAddress((void**)&w2sf, g_W2sf);
    cudaGetSymbolAddress((void**)&w2nf, g_W2nf);
    cudaGetSymbolAddress((void**)&bf,   g_bf);

    const int TB = 256;
    int nblk_n = (NN + TB - 1) / TB;
    int nblk_e = (NE + TB - 1) / TB;
    int ntiles = (NN + 1023) / 1024;

    // CSR build
    k_zero_counts<<<nblk_n, TB>>>();
    k_count<<<nblk_e, TB>>>(edst);
    k_scan_tiles<<<ntiles, 1024>>>();
    k_scan_sums<<<1, 64>>>(ntiles);
    k_scan_fix<<<nblk_n, TB>>>();
    k_fill<<<nblk_e, TB>>>(esrc, edst);

    // fold fc into layer 2
    k_fuse_weights<<<(HID * NCLS + TB - 1) / TB, TB>>>(W2s, W2n, b2, Wfc, bfc);

    dim3 gBig(HID / 128, (NN + 63) / 64);     // BM=64, BN=128 for Nc=256
    dim3 gSmall(NCLS / 64, (NN + 127) / 128); // BM=128, BN=64 for Nc=64

    // layer 0: agg at 128-dim, then h0 = x@W0s + agg0@W0n + b0
    k_gather_mean<INF><<<(NN * (INF / 4) + TB - 1) / TB, TB>>>(x, agg);
    k_gemm<64, 128><<<gBig, TB>>>(x, W0s, INF, agg, W0n, INF, b0, nullptr, h0, NN, HID);

    // layer 1: agg at 256-dim, h1 = h0@W1s + agg1@W1n + b1
    k_gather_mean<HID><<<(NN * (HID / 4) + TB - 1) / TB, TB>>>(h0, agg);
    k_gemm<64, 128><<<gBig, TB>>>(h0, W1s, HID, agg, W1n, HID, b1, nullptr, h1, NN, HID);

    // layer 2 + fc folded: t = h1@W2nf (64-dim), aggt = mean(t),
    // out = h1@W2sf + aggt + bf
    float* t    = agg;
    float* aggt = agg + (size_t)NN * NCLS;
    k_gemm<128, 64><<<gSmall, TB>>>(h1, w2nf, HID, nullptr, nullptr, 0, nullptr, nullptr, t, NN, NCLS);
    k_gather_mean<NCLS><<<(NN * (NCLS / 4) + TB - 1) / TB, TB>>>(t, aggt);
    k_gemm<128, 64><<<gSmall, TB>>>(h1, w2sf, HID, nullptr, nullptr, 0, bf, aggt, out, NN, NCLS);
}

// round 3
// speedup vs baseline: 2.9878x; 2.9878x over previous
#include <cuda_runtime.h>
#include <math.h>

#define NN 50000
#define NE 800000
#define INF 128
#define HID 256
#define NCLS 64

// ---------------- device scratch ----------------
__device__ int   g_deg[NN];
__device__ int   g_cursor[NN];
__device__ int   g_off[NN + 1];
__device__ int   g_csr[NE];
__device__ float g_invdeg[NN];
__device__ int   g_tsum[64];
__device__ __align__(16) float g_U[(size_t)NN * 256];      // x @ Cbig
__device__ __align__(16) float g_s[(size_t)2 * NN * 64];   // s2, s1
__device__ __align__(16) float g_pre[5 * 256 * 64];        // Us, Un, Q0, Q1, Q2
__device__ __align__(16) float g_C[128 * 256];             // [C0|C1|C2|C3]
__device__ float g_r[3 * 64];                              // r0, r1, r2
__device__ float g_e1[NN];
__device__ float g_e2[NN];

// ---------------- CSR build ----------------
__global__ void k_zero_counts() {
    int i = blockIdx.x * blockDim.x + threadIdx.x;
    if (i < NN) { g_deg[i] = 0; g_cursor[i] = 0; }
}

__global__ void k_count(const int* __restrict__ dst) {
    int e = blockIdx.x * blockDim.x + threadIdx.x;
    if (e < NE) atomicAdd(&g_deg[dst[e]], 1);
}

__global__ void k_scan_tiles() {
    __shared__ int sh[1024];
    int t = threadIdx.x;
    int i = blockIdx.x * 1024 + t;
    int v = (i < NN) ? g_deg[i] : 0;
    sh[t] = v;
    __syncthreads();
    for (int d = 1; d < 1024; d <<= 1) {
        int x = 0;
        if (t >= d) x = sh[t - d];
        __syncthreads();
        sh[t] += x;
        __syncthreads();
    }
    if (i < NN) g_off[i] = sh[t] - v;
    if (t == 1023) g_tsum[blockIdx.x] = sh[t];
}

__global__ void k_scan_sums(int ntiles) {
    __shared__ int sh[64];
    int t = threadIdx.x;
    int v = (t < ntiles) ? g_tsum[t] : 0;
    sh[t] = v;
    __syncthreads();
    for (int d = 1; d < 64; d <<= 1) {
        int x = 0;
        if (t >= d) x = sh[t - d];
        __syncthreads();
        sh[t] += x;
        __syncthreads();
    }
    if (t < ntiles) g_tsum[t] = sh[t] - v;
}

__global__ void k_scan_fix() {
    int i = blockIdx.x * blockDim.x + threadIdx.x;
    if (i < NN) {
        g_off[i] += g_tsum[i >> 10];
        g_invdeg[i] = 1.0f / fmaxf((float)g_deg[i], 1.0f);
    }
    if (i == 0) g_off[NN] = NE;
}

__global__ void k_fill(const int* __restrict__ src, const int* __restrict__ dst) {
    int e = blockIdx.x * blockDim.x + threadIdx.x;
    if (e < NE) {
        int d = dst[e];
        int pos = g_off[d] + atomicAdd(&g_cursor[d], 1);
        g_csr[pos] = src[e];
    }
}

// e1 = S·1 indicator, e2 = S·e1
__global__ void k_e12() {
    int i = blockIdx.x * blockDim.x + threadIdx.x;
    if (i >= NN) return;
    g_e1[i] = (g_deg[i] > 0) ? 1.0f : 0.0f;
    int s = g_off[i], e = g_off[i + 1];
    float acc = 0.f;
    for (int j = s; j < e; ++j) acc += (g_deg[g_csr[j]] > 0) ? 1.0f : 0.0f;
    g_e2[i] = acc * g_invdeg[i];
}

// ---------------- small dense GEMM: out = A0@B0 (+ A1@B1) ----------------
// A: M x K (lda = K), B: K x Nn (ldb = Nn), out: M x Nn with row stride ldout
__global__ void k_small(const float* __restrict__ A0, const float* __restrict__ B0,
                        const float* __restrict__ A1, const float* __restrict__ B1,
                        float* __restrict__ out, int M, int K, int Nn, int ldout) {
    int idx = blockIdx.x * blockDim.x + threadIdx.x;
    if (idx >= M * Nn) return;
    int r = idx / Nn, c = idx % Nn;
    float acc = 0.f;
    #pragma unroll 8
    for (int k = 0; k < K; ++k) acc += A0[r * K + k] * B0[k * Nn + c];
    if (A1 != nullptr) {
        #pragma unroll 8
        for (int k = 0; k < K; ++k) acc += A1[r * K + k] * B1[k * Nn + c];
    }
    out[r * ldout + c] = acc;
}

// r0 = b0@Q0 + b1@Us + b2@Wfc + bfc ; r1 = b0@Q1 + b1@Un ; r2 = b0@Q2
__global__ void k_rvec(const float* __restrict__ b0, const float* __restrict__ b1,
                       const float* __restrict__ b2, const float* __restrict__ bfc,
                       const float* __restrict__ Wfc) {
    const float* Us = g_pre;
    const float* Un = g_pre + 256 * 64;
    const float* Q0 = g_pre + 2 * 256 * 64;
    const float* Q1 = g_pre + 3 * 256 * 64;
    const float* Q2 = g_pre + 4 * 256 * 64;
    int t = threadIdx.x;          // 0..191
    int which = t / 64, c = t % 64;
    float acc = 0.f;
    if (which == 0) {
        for (int k = 0; k < 256; ++k)
            acc += b0[k] * Q0[k * 64 + c] + b1[k] * Us[k * 64 + c] + b2[k] * Wfc[k * 64 + c];
        acc += bfc[c];
    } else if (which == 1) {
        for (int k = 0; k < 256; ++k)
            acc += b0[k] * Q1[k * 64 + c] + b1[k] * Un[k * 64 + c];
    } else {
        for (int k = 0; k < 256; ++k)
            acc += b0[k] * Q2[k * 64 + c];
    }
    g_r[t] = acc;
}

// ---------------- 64-dim mean gather with fused add (+ optional bias) ----------
// out[n] = invdeg[n] * sum_{nbr} src[nbr] + add[n]  (+ r0 + e1[n]*r1 + e2[n]*r2)
// lds/lda/ldo are row strides in float4 units
__global__ void k_gather64(const float4* __restrict__ src, int lds,
                           const float4* __restrict__ add, int lda,
                           float4* __restrict__ out, int ldo, int with_bias) {
    int gtid = blockIdx.x * blockDim.x + threadIdx.x;
    int node = gtid >> 4;
    int c = gtid & 15;
    if (node >= NN) return;
    int s = g_off[node], e = g_off[node + 1];
    float4 acc = make_float4(0.f, 0.f, 0.f, 0.f);
    for (int idx = s; idx < e; ++idx) {
        int sn = g_csr[idx];
        float4 v = src[(size_t)sn * lds + c];
        acc.x += v.x; acc.y += v.y; acc.z += v.z; acc.w += v.w;
    }
    float w = g_invdeg[node];
    float4 r = add[(size_t)node * lda + c];
    r.x += acc.x * w; r.y += acc.y * w; r.z += acc.z * w; r.w += acc.w * w;
    if (with_bias) {
        float a = g_e1[node], b = g_e2[node];
        const float4* r0 = (const float4*)g_r;
        const float4* r1 = r0 + 16;
        const float4* r2 = r0 + 32;
        float4 v0 = r0[c], v1 = r1[c], v2 = r2[c];
        r.x += v0.x + a * v1.x + b * v2.x;
        r.y += v0.y + a * v1.y + b * v2.y;
        r.z += v0.z + a * v1.z + b * v2.z;
        r.w += v0.w + a * v1.w + b * v2.w;
    }
    out[(size_t)node * ldo + c] = r;
}

// ---------------- main GEMM (R1 scalar engine): C = A @ B ----------------
__global__ __launch_bounds__(256)
void k_gemm(const float* __restrict__ A, const float* __restrict__ B, int K,
            float* __restrict__ C, int M, int Nc) {
    constexpr int BM = 64, BN = 64, BK = 16;
    __shared__ float As[BK][BM];
    __shared__ float Bs[BK][BN];

    int tid = threadIdx.x;
    int tx = tid & 15, ty = tid >> 4;
    int bm = blockIdx.y * BM, bn = blockIdx.x * BN;

    int a_r = tid >> 2;
    int a_c = (tid & 3) * 4;
    int b_r = tid >> 4;
    int b_c = (tid & 15) * 4;

    float acc[4][4] = {};

    for (int k0 = 0; k0 < K; k0 += BK) {
        float4 av = make_float4(0.f, 0.f, 0.f, 0.f);
        int row = bm + a_r;
        if (row < M) av = *(const float4*)(A + (size_t)row * K + k0 + a_c);
        As[a_c + 0][a_r] = av.x;
        As[a_c + 1][a_r] = av.y;
        As[a_c + 2][a_r] = av.z;
        As[a_c + 3][a_r] = av.w;
        float4 bv = *(const float4*)(B + (size_t)(k0 + b_r) * Nc + bn + b_c);
        *(float4*)&Bs[b_r][b_c] = bv;
        __syncthreads();
        #pragma unroll
        for (int k = 0; k < BK; ++k) {
            float4 a = *(const float4*)&As[k][ty * 4];
            float4 b = *(const float4*)&Bs[k][tx * 4];
            acc[0][0] += a.x * b.x; acc[0][1] += a.x * b.y; acc[0][2] += a.x * b.z; acc[0][3] += a.x * b.w;
            acc[1][0] += a.y * b.x; acc[1][1] += a.y * b.y; acc[1][2] += a.y * b.z; acc[1][3] += a.y * b.w;
            acc[2][0] += a.z * b.x; acc[2][1] += a.z * b.y; acc[2][2] += a.z * b.z; acc[2][3] += a.z * b.w;
            acc[3][0] += a.w * b.x; acc[3][1] += a.w * b.y; acc[3][2] += a.w * b.z; acc[3][3] += a.w * b.w;
        }
        __syncthreads();
    }

    #pragma unroll
    for (int i = 0; i < 4; ++i) {
        int row = bm + ty * 4 + i;
        if (row >= M) continue;
        int col = bn + tx * 4;
        *(float4*)(C + (size_t)row * Nc + col) =
            make_float4(acc[i][0], acc[i][1], acc[i][2], acc[i][3]);
    }
}

// ---------------- launch ----------------
extern "C" void kernel_launch(void* const* d_in, const int* in_sizes, int n_in,
                              void* d_out, int out_size) {
    const float* x    = (const float*)d_in[0];
    const int*   esrc = (const int*)d_in[1];
    const int*   edst = (const int*)d_in[2];
    const float* W0s  = (const float*)d_in[3];
    const float* W0n  = (const float*)d_in[4];
    const float* b0   = (const float*)d_in[5];
    const float* W1s  = (const float*)d_in[6];
    const float* W1n  = (const float*)d_in[7];
    const float* b1   = (const float*)d_in[8];
    const float* W2s  = (const float*)d_in[9];
    const float* W2n  = (const float*)d_in[10];
    const float* b2   = (const float*)d_in[11];
    const float* Wfc  = (const float*)d_in[12];
    const float* bfc  = (const float*)d_in[13];
    float* out = (float*)d_out;

    float *U, *sbuf, *pre, *Cbig;
    cudaGetSymbolAddress((void**)&U,    g_U);
    cudaGetSymbolAddress((void**)&sbuf, g_s);
    cudaGetSymbolAddress((void**)&pre,  g_pre);
    cudaGetSymbolAddress((void**)&Cbig, g_C);

    float* Us = pre;
    float* Un = pre + 256 * 64;
    float* Q0 = pre + 2 * 256 * 64;
    float* Q1 = pre + 3 * 256 * 64;
    float* Q2 = pre + 4 * 256 * 64;

    const int TB = 256;
    int nblk_n = (NN + TB - 1) / TB;
    int nblk_e = (NE + TB - 1) / TB;
    int ntiles = (NN + 1023) / 1024;

    // ---- CSR build ----
    k_zero_counts<<<nblk_n, TB>>>();
    k_count<<<nblk_e, TB>>>(edst);
    k_scan_tiles<<<ntiles, 1024>>>();
    k_scan_sums<<<1, 64>>>(ntiles);
    k_scan_fix<<<nblk_n, TB>>>();
    k_fill<<<nblk_e, TB>>>(esrc, edst);
    k_e12<<<nblk_n, TB>>>();

    // ---- weight precompute: collapse the whole linear network ----
    int nb_256x64 = (256 * 64 + TB - 1) / TB;
    int nb_128x64 = (128 * 64 + TB - 1) / TB;
    // Stage A: Us = W2s@Wfc, Un = W2n@Wfc
    k_small<<<nb_256x64, TB>>>(W2s, Wfc, nullptr, nullptr, Us, 256, 256, 64, 64);
    k_small<<<nb_256x64, TB>>>(W2n, Wfc, nullptr, nullptr, Un, 256, 256, 64, 64);
    // Stage B: Q0 = W1s@Us ; Q1 = W1n@Us + W1s@Un ; Q2 = W1n@Un
    k_small<<<nb_256x64, TB>>>(W1s, Us, nullptr, nullptr, Q0, 256, 256, 64, 64);
    k_small<<<nb_256x64, TB>>>(W1n, Us, W1s, Un,          Q1, 256, 256, 64, 64);
    k_small<<<nb_256x64, TB>>>(W1n, Un, nullptr, nullptr, Q2, 256, 256, 64, 64);
    // Stage C: Cbig = [C0|C1|C2|C3]  (128 x 256, ldout = 256)
    k_small<<<nb_128x64, TB>>>(W0s, Q0, nullptr, nullptr, Cbig + 0,   128, 256, 64, 256);
    k_small<<<nb_128x64, TB>>>(W0n, Q0, W0s, Q1,          Cbig + 64,  128, 256, 64, 256);
    k_small<<<nb_128x64, TB>>>(W0n, Q1, W0s, Q2,          Cbig + 128, 128, 256, 64, 256);
    k_small<<<nb_128x64, TB>>>(W0n, Q2, nullptr, nullptr, Cbig + 192, 128, 256, 64, 256);
    // bias vectors
    k_rvec<<<1, 192>>>(b0, b1, b2, bfc, Wfc);

    // ---- main GEMM: U = x @ Cbig  (50000 x 128 x 256) ----
    dim3 gMain(256 / 64, (NN + 63) / 64);
    k_gemm<<<gMain, TB>>>(x, Cbig, INF, U, NN, 256);

    // ---- Horner aggregation: out = u0 + S(u1 + S(u2 + S(u3))) + bias ----
    const float4* Uf = (const float4*)U;       // row stride 64 float4s
    float4* s2 = (float4*)sbuf;                // NN x 16 float4
    float4* s1 = (float4*)(sbuf + (size_t)NN * 64);
    int gblk = (NN * 16 + TB - 1) / TB;
    // s2 = u2 + S(u3)
    k_gather64<<<gblk, TB>>>(Uf + 48, 64, Uf + 32, 64, s2, 16, 0);
    // s1 = u1 + S(s2)
    k_gather64<<<gblk, TB>>>(s2, 16, Uf + 16, 64, s1, 16, 0);
    // out = u0 + S(s1) + r0 + e1*r1 + e2*r2
    k_gather64<<<gblk, TB>>>(s1, 16, Uf + 0, 64, (float4*)out, 16, 1);
}

// round 5
// speedup vs baseline: 3.2089x; 1.0740x over previous
#include <cuda_runtime.h>
#include <cuda_bf16.h>
#include <math.h>
#include <cstdint>

#define NN 50000
#define NE 800000
#define INF 128
#define HID 256
#define NCLS 64

// ---------------- device scratch ----------------
__device__ int   g_deg[NN];
__device__ int   g_cursor[NN];
__device__ int   g_off[NN + 1];
__device__ int   g_csr[NE];
__device__ float g_invdeg[NN];
__device__ int   g_tsum[64];
__device__ __align__(16) float g_U[(size_t)NN * 256];      // x @ Cbig
__device__ __align__(16) float g_s[(size_t)2 * NN * 64];   // s2, s1
__device__ __align__(16) float g_pre[5 * 256 * 64];        // Us, Un, Q0, Q1, Q2
__device__ __align__(16) __nv_bfloat16 g_CTh[256 * 128];   // Cbig^T hi  [n][k]
__device__ __align__(16) __nv_bfloat16 g_CTl[256 * 128];   // Cbig^T lo
__device__ float g_r[3 * 64];
__device__ float g_e1[NN];
__device__ float g_e2[NN];

// ---------------- CSR build ----------------
__global__ void k_zero_counts() {
    int i = blockIdx.x * blockDim.x + threadIdx.x;
    if (i < NN) { g_deg[i] = 0; g_cursor[i] = 0; }
}

__global__ void k_count(const int* __restrict__ dst) {
    int e = blockIdx.x * blockDim.x + threadIdx.x;
    if (e < NE) atomicAdd(&g_deg[dst[e]], 1);
}

__global__ void k_scan_tiles() {
    __shared__ int sh[1024];
    int t = threadIdx.x;
    int i = blockIdx.x * 1024 + t;
    int v = (i < NN) ? g_deg[i] : 0;
    sh[t] = v;
    __syncthreads();
    for (int d = 1; d < 1024; d <<= 1) {
        int x = 0;
        if (t >= d) x = sh[t - d];
        __syncthreads();
        sh[t] += x;
        __syncthreads();
    }
    if (i < NN) g_off[i] = sh[t] - v;
    if (t == 1023) g_tsum[blockIdx.x] = sh[t];
}

__global__ void k_scan_sums(int ntiles) {
    __shared__ int sh[64];
    int t = threadIdx.x;
    int v = (t < ntiles) ? g_tsum[t] : 0;
    sh[t] = v;
    __syncthreads();
    for (int d = 1; d < 64; d <<= 1) {
        int x = 0;
        if (t >= d) x = sh[t - d];
        __syncthreads();
        sh[t] += x;
        __syncthreads();
    }
    if (t < ntiles) g_tsum[t] = sh[t] - v;
}

__global__ void k_scan_fix() {
    int i = blockIdx.x * blockDim.x + threadIdx.x;
    if (i < NN) {
        g_off[i] += g_tsum[i >> 10];
        g_invdeg[i] = 1.0f / fmaxf((float)g_deg[i], 1.0f);
    }
    if (i == 0) g_off[NN] = NE;
}

__global__ void k_fill(const int* __restrict__ src, const int* __restrict__ dst) {
    int e = blockIdx.x * blockDim.x + threadIdx.x;
    if (e < NE) {
        int d = dst[e];
        int pos = g_off[d] + atomicAdd(&g_cursor[d], 1);
        g_csr[pos] = src[e];
    }
}

__global__ void k_e12() {
    int i = blockIdx.x * blockDim.x + threadIdx.x;
    if (i >= NN) return;
    g_e1[i] = (g_deg[i] > 0) ? 1.0f : 0.0f;
    int s = g_off[i], e = g_off[i + 1];
    float acc = 0.f;
    for (int j = s; j < e; ++j) acc += (g_deg[g_csr[j]] > 0) ? 1.0f : 0.0f;
    g_e2[i] = acc * g_invdeg[i];
}

// ---------------- small dense GEMM: out = A0@B0 (+ A1@B1) ----------------
__global__ void k_small(const float* __restrict__ A0, const float* __restrict__ B0,
                        const float* __restrict__ A1, const float* __restrict__ B1,
                        float* __restrict__ out, int M, int K, int Nn, int ldout) {
    int idx = blockIdx.x * blockDim.x + threadIdx.x;
    if (idx >= M * Nn) return;
    int r = idx / Nn, c = idx % Nn;
    float acc = 0.f;
    #pragma unroll 8
    for (int k = 0; k < K; ++k) acc += A0[r * K + k] * B0[k * Nn + c];
    if (A1 != nullptr) {
        #pragma unroll 8
        for (int k = 0; k < K; ++k) acc += A1[r * K + k] * B1[k * Nn + c];
    }
    out[r * ldout + c] = acc;
}

// stage C: write transposed bf16 hi/lo split:  CT[n][k]
__global__ void k_smallT(const float* __restrict__ A0, const float* __restrict__ B0,
                         const float* __restrict__ A1, const float* __restrict__ B1,
                         __nv_bfloat16* __restrict__ outh, __nv_bfloat16* __restrict__ outl) {
    int idx = blockIdx.x * blockDim.x + threadIdx.x;
    if (idx >= 128 * 64) return;
    int r = idx / 64, c = idx % 64;       // r = k index, c = n-local
    float acc = 0.f;
    #pragma unroll 8
    for (int k = 0; k < 256; ++k) acc += A0[r * 256 + k] * B0[k * 64 + c];
    if (A1 != nullptr) {
        #pragma unroll 8
        for (int k = 0; k < 256; ++k) acc += A1[r * 256 + k] * B1[k * 64 + c];
    }
    __nv_bfloat16 h = __float2bfloat16(acc);
    outh[c * 128 + r] = h;
    outl[c * 128 + r] = __float2bfloat16(acc - __bfloat162float(h));
}

// r0 = b0@Q0 + b1@Us + b2@Wfc + bfc ; r1 = b0@Q1 + b1@Un ; r2 = b0@Q2
__global__ void k_rvec(const float* __restrict__ b0, const float* __restrict__ b1,
                       const float* __restrict__ b2, const float* __restrict__ bfc,
                       const float* __restrict__ Wfc) {
    const float* Us = g_pre;
    const float* Un = g_pre + 256 * 64;
    const float* Q0 = g_pre + 2 * 256 * 64;
    const float* Q1 = g_pre + 3 * 256 * 64;
    const float* Q2 = g_pre + 4 * 256 * 64;
    int t = threadIdx.x;
    int which = t / 64, c = t % 64;
    float acc = 0.f;
    if (which == 0) {
        for (int k = 0; k < 256; ++k)
            acc += b0[k] * Q0[k * 64 + c] + b1[k] * Us[k * 64 + c] + b2[k] * Wfc[k * 64 + c];
        acc += bfc[c];
    } else if (which == 1) {
        for (int k = 0; k < 256; ++k)
            acc += b0[k] * Q1[k * 64 + c] + b1[k] * Un[k * 64 + c];
    } else {
        for (int k = 0; k < 256; ++k)
            acc += b0[k] * Q2[k * 64 + c];
    }
    g_r[t] = acc;
}

// ---------------- 64-dim mean gather with fused add ----------------
__global__ void k_gather64(const float4* __restrict__ src, int lds,
                           const float4* __restrict__ add, int lda,
                           float4* __restrict__ out, int ldo, int with_bias) {
    int gtid = blockIdx.x * blockDim.x + threadIdx.x;
    int node = gtid >> 4;
    int c = gtid & 15;
    if (node >= NN) return;
    int s = g_off[node], e = g_off[node + 1];
    float4 acc = make_float4(0.f, 0.f, 0.f, 0.f);
    for (int idx = s; idx < e; ++idx) {
        int sn = g_csr[idx];
        float4 v = src[(size_t)sn * lds + c];
        acc.x += v.x; acc.y += v.y; acc.z += v.z; acc.w += v.w;
    }
    float w = g_invdeg[node];
    float4 r = add[(size_t)node * lda + c];
    r.x += acc.x * w; r.y += acc.y * w; r.z += acc.z * w; r.w += acc.w * w;
    if (with_bias) {
        float a = g_e1[node], b = g_e2[node];
        const float4* r0 = (const float4*)g_r;
        const float4* r1 = r0 + 16;
        const float4* r2 = r0 + 32;
        float4 v0 = r0[c], v1 = r1[c], v2 = r2[c];
        r.x += v0.x + a * v1.x + b * v2.x;
        r.y += v0.y + a * v1.y + b * v2.y;
        r.z += v0.z + a * v1.z + b * v2.z;
        r.w += v0.w + a * v1.w + b * v2.w;
    }
    out[(size_t)node * ldo + c] = r;
}

// ---------------- mma.sync bf16 split-precision GEMM ----------------
// U[M x 256] = x[M x 128] @ Cbig[128 x 256]
// A = x split to bf16 hi/lo; B = CT (col-major B == CT[n][k]) hi/lo precomputed.
// 3 passes: Ah@Bh + Ah@Bl + Al@Bh into fp32 accumulators.
// Block: 256 thr (8 warps, 2m x 4n), tile 128(M) x 128(N), K=128 in smem.
#define LDK 136                  // smem row stride in halves (bank-spread)
#define SM_AH 0
#define SM_AL (128 * LDK)
#define SM_BH (2 * 128 * LDK)
#define SM_BL (3 * 128 * LDK)
#define SM_HALVES (4 * 128 * LDK)

#define MMA16816(c, a, b0_, b1_) \
    asm volatile("mma.sync.aligned.m16n8k16.row.col.f32.bf16.bf16.f32 " \
        "{%0,%1,%2,%3}, {%4,%5,%6,%7}, {%8,%9}, {%0,%1,%2,%3};" \
        : "+f"((c)[0]), "+f"((c)[1]), "+f"((c)[2]), "+f"((c)[3]) \
        : "r"((a)[0]), "r"((a)[1]), "r"((a)[2]), "r"((a)[3]), \
          "r"(b0_), "r"(b1_))

__global__ __launch_bounds__(256, 1)
void k_wgemm(const float* __restrict__ x, const __nv_bfloat16* __restrict__ CTh,
             const __nv_bfloat16* __restrict__ CTl, float* __restrict__ U, int M) {
    extern __shared__ __nv_bfloat16 sm[];
    __nv_bfloat16* Ah = sm + SM_AH;
    __nv_bfloat16* Al = sm + SM_AL;
    __nv_bfloat16* Bh = sm + SM_BH;
    __nv_bfloat16* Bl = sm + SM_BL;

    const int tid = threadIdx.x;
    const int bm = blockIdx.y * 128;
    const int bn = blockIdx.x * 128;

    // ---- stage A: rows bm..bm+127 of x -> bf16 hi/lo ----
    {
        int r = tid >> 1;                 // 0..127
        int half = tid & 1;               // k 0-63 / 64-127
        int grow = bm + r;
        const float4* xr = (const float4*)(x + (size_t)grow * 128 + half * 64);
        __nv_bfloat16* ah = Ah + r * LDK + half * 64;
        __nv_bfloat16* al = Al + r * LDK + half * 64;
        #pragma unroll
        for (int j = 0; j < 8; ++j) {     // 8 halves per iter
            float f[8];
            if (grow < M) {
                float4 v0 = xr[2 * j], v1 = xr[2 * j + 1];
                f[0] = v0.x; f[1] = v0.y; f[2] = v0.z; f[3] = v0.w;
                f[4] = v1.x; f[5] = v1.y; f[6] = v1.z; f[7] = v1.w;
            } else {
                #pragma unroll
                for (int e = 0; e < 8; ++e) f[e] = 0.f;
            }
            uint32_t hp[4], lp[4];
            #pragma unroll
            for (int e = 0; e < 4; ++e) {
                __nv_bfloat16 h0 = __float2bfloat16(f[2 * e]);
                __nv_bfloat16 h1 = __float2bfloat16(f[2 * e + 1]);
                float l0 = f[2 * e]     - __bfloat162float(h0);
                float l1 = f[2 * e + 1] - __bfloat162float(h1);
                __nv_bfloat162 hh = __halves2bfloat162(h0, h1);
                __nv_bfloat162 lv = __halves2bfloat162(__float2bfloat16(l0),
                                                       __float2bfloat16(l1));
                hp[e] = *(uint32_t*)&hh;
                lp[e] = *(uint32_t*)&lv;
            }
            *(uint4*)(ah + 8 * j) = make_uint4(hp[0], hp[1], hp[2], hp[3]);
            *(uint4*)(al + 8 * j) = make_uint4(lp[0], lp[1], lp[2], lp[3]);
        }
    }
    // ---- stage B: CT rows bn..bn+127 (hi/lo) ----
    {
        int r = tid >> 1;
        int half = tid & 1;
        const uint4* sh = (const uint4*)(CTh + (size_t)(bn + r) * 128 + half * 64);
        const uint4* sl = (const uint4*)(CTl + (size_t)(bn + r) * 128 + half * 64);
        uint4* dh = (uint4*)(Bh + r * LDK + half * 64);
        uint4* dl = (uint4*)(Bl + r * LDK + half * 64);
        #pragma unroll
        for (int j = 0; j < 8; ++j) { dh[j] = sh[j]; dl[j] = sl[j]; }
    }
    __syncthreads();

    const int w = tid >> 5, lane = tid & 31;
    const int wm = (w >> 2) * 64;          // warp m offset in tile
    const int wn = (w & 3) * 32;           // warp n offset in tile
    const int lr = lane >> 2;              // 0..7
    const int lc = (lane & 3) * 2;         // 0,2,4,6

    float acc[4][4][4];
    #pragma unroll
    for (int i = 0; i < 4; ++i)
        #pragma unroll
        for (int j = 0; j < 4; ++j)
            #pragma unroll
            for (int e = 0; e < 4; ++e) acc[i][j][e] = 0.f;

    #pragma unroll
    for (int pass = 0; pass < 3; ++pass) {
        const __nv_bfloat16* As = (pass == 2) ? Al : Ah;
        const __nv_bfloat16* Bs = (pass == 1) ? Bl : Bh;
        #pragma unroll
        for (int ks = 0; ks < 8; ++ks) {
            int kb = ks * 16;
            uint32_t a[4][4];
            #pragma unroll
            for (int fm = 0; fm < 4; ++fm) {
                int r = wm + fm * 16 + lr;
                a[fm][0] = *(const uint32_t*)&As[r * LDK + kb + lc];
                a[fm][1] = *(const uint32_t*)&As[(r + 8) * LDK + kb + lc];
                a[fm][2] = *(const uint32_t*)&As[r * LDK + kb + 8 + lc];
                a[fm][3] = *(const uint32_t*)&As[(r + 8) * LDK + kb + 8 + lc];
            }
            #pragma unroll
            for (int fn = 0; fn < 4; ++fn) {
                int n = wn + fn * 8 + lr;
                uint32_t b0 = *(const uint32_t*)&Bs[n * LDK + kb + lc];
                uint32_t b1 = *(const uint32_t*)&Bs[n * LDK + kb + 8 + lc];
                #pragma unroll
                for (int fm = 0; fm < 4; ++fm)
                    MMA16816(acc[fm][fn], a[fm], b0, b1);
            }
        }
    }

    // ---- epilogue ----
    #pragma unroll
    for (int fm = 0; fm < 4; ++fm) {
        int r0 = bm + wm + fm * 16 + lr;
        int r1 = r0 + 8;
        #pragma unroll
        for (int fn = 0; fn < 4; ++fn) {
            int col = bn + wn + fn * 8 + lc;
            if (r0 < M)
                *(float2*)(U + (size_t)r0 * 256 + col) =
                    make_float2(acc[fm][fn][0], acc[fm][fn][1]);
            if (r1 < M)
                *(float2*)(U + (size_t)r1 * 256 + col) =
                    make_float2(acc[fm][fn][2], acc[fm][fn][3]);
        }
    }
}

// ---------------- launch ----------------
extern "C" void kernel_launch(void* const* d_in, const int* in_sizes, int n_in,
                              void* d_out, int out_size) {
    const float* x    = (const float*)d_in[0];
    const int*   esrc = (const int*)d_in[1];
    const int*   edst = (const int*)d_in[2];
    const float* W0s  = (const float*)d_in[3];
    const float* W0n  = (const float*)d_in[4];
    const float* b0   = (const float*)d_in[5];
    const float* W1s  = (const float*)d_in[6];
    const float* W1n  = (const float*)d_in[7];
    const float* b1   = (const float*)d_in[8];
    const float* W2s  = (const float*)d_in[9];
    const float* W2n  = (const float*)d_in[10];
    const float* b2   = (const float*)d_in[11];
    const float* Wfc  = (const float*)d_in[12];
    const float* bfc  = (const float*)d_in[13];
    float* out = (float*)d_out;

    float *U, *sbuf, *pre;
    __nv_bfloat16 *CTh, *CTl;
    cudaGetSymbolAddress((void**)&U,    g_U);
    cudaGetSymbolAddress((void**)&sbuf, g_s);
    cudaGetSymbolAddress((void**)&pre,  g_pre);
    cudaGetSymbolAddress((void**)&CTh,  g_CTh);
    cudaGetSymbolAddress((void**)&CTl,  g_CTl);

    float* Us = pre;
    float* Un = pre + 256 * 64;
    float* Q0 = pre + 2 * 256 * 64;
    float* Q1 = pre + 3 * 256 * 64;
    float* Q2 = pre + 4 * 256 * 64;

    const int TB = 256;
    int nblk_n = (NN + TB - 1) / TB;
    int nblk_e = (NE + TB - 1) / TB;
    int ntiles = (NN + 1023) / 1024;

    // ---- CSR build ----
    k_zero_counts<<<nblk_n, TB>>>();
    k_count<<<nblk_e, TB>>>(edst);
    k_scan_tiles<<<ntiles, 1024>>>();
    k_scan_sums<<<1, 64>>>(ntiles);
    k_scan_fix<<<nblk_n, TB>>>();
    k_fill<<<nblk_e, TB>>>(esrc, edst);
    k_e12<<<nblk_n, TB>>>();

    // ---- weight precompute ----
    int nb_256x64 = (256 * 64 + TB - 1) / TB;
    int nb_128x64 = (128 * 64 + TB - 1) / TB;
    k_small<<<nb_256x64, TB>>>(W2s, Wfc, nullptr, nullptr, Us, 256, 256, 64, 64);
    k_small<<<nb_256x64, TB>>>(W2n, Wfc, nullptr, nullptr, Un, 256, 256, 64, 64);
    k_small<<<nb_256x64, TB>>>(W1s, Us, nullptr, nullptr, Q0, 256, 256, 64, 64);
    k_small<<<nb_256x64, TB>>>(W1n, Us, W1s, Un,          Q1, 256, 256, 64, 64);
    k_small<<<nb_256x64, TB>>>(W1n, Un, nullptr, nullptr, Q2, 256, 256, 64, 64);
    k_smallT<<<nb_128x64, TB>>>(W0s, Q0, nullptr, nullptr, CTh + 0 * 8192, CTl + 0 * 8192);
    k_smallT<<<nb_128x64, TB>>>(W0n, Q0, W0s, Q1,          CTh + 1 * 8192, CTl + 1 * 8192);
    k_smallT<<<nb_128x64, TB>>>(W0n, Q1, W0s, Q2,          CTh + 2 * 8192, CTl + 2 * 8192);
    k_smallT<<<nb_128x64, TB>>>(W0n, Q2, nullptr, nullptr, CTh + 3 * 8192, CTl + 3 * 8192);
    k_rvec<<<1, 192>>>(b0, b1, b2, bfc, Wfc);

    // ---- main GEMM on mma.sync tensor path ----
    size_t smem_bytes = (size_t)SM_HALVES * sizeof(__nv_bfloat16);
    cudaFuncSetAttribute(k_wgemm, cudaFuncAttributeMaxDynamicSharedMemorySize,
                         (int)smem_bytes);
    dim3 gG(2, (NN + 127) / 128);
    k_wgemm<<<gG, 256, smem_bytes>>>(x, CTh, CTl, U, NN);

    // ---- Horner aggregation ----
    const float4* Uf = (const float4*)U;
    float4* s2 = (float4*)sbuf;
    float4* s1 = (float4*)(sbuf + (size_t)NN * 64);
    int gblk = (NN * 16 + TB - 1) / TB;
    k_gather64<<<gblk, TB>>>(Uf + 48, 64, Uf + 32, 64, s2, 16, 0);
    k_gather64<<<gblk, TB>>>(s2, 16, Uf + 16, 64, s1, 16, 0);
    k_gather64<<<gblk, TB>>>(s1, 16, Uf + 0, 64, (float4*)out, 16, 1);
}

// round 6
// speedup vs baseline: 4.1041x; 1.2790x over previous
#include <cuda_runtime.h>
#include <cuda_bf16.h>
#include <math.h>
#include <cstdint>

#define NN 50000
#define NE 800000
#define INF 128
#define HID 256
#define NCLS 64

// ---------------- device scratch ----------------
__device__ int   g_deg[NN];
__device__ int   g_cursor[NN];
__device__ int   g_off[NN + 1];
__device__ int   g_csr[NE];
__device__ float g_invdeg[NN];
__device__ int   g_tsum[64];
__device__ __align__(16) float g_U[(size_t)NN * 256];      // x @ Cbig
__device__ __align__(16) float g_s[(size_t)2 * NN * 64];   // s2, s1
// g_pre layout: Us=0, Un=16384, Q0=32768, Q1=49152, Q2=65536
__device__ __align__(16) float g_pre[5 * 256 * 64];
__device__ __align__(16) __nv_bfloat16 g_CTh[256 * 128];   // Cbig^T hi [n][k]
__device__ __align__(16) __nv_bfloat16 g_CTl[256 * 128];   // Cbig^T lo
__device__ float g_r[3 * 64];
__device__ float g_e1[NN];
__device__ float g_e2[NN];

// ---------------- CSR build ----------------
__global__ void k_zero_counts() {
    int i = blockIdx.x * blockDim.x + threadIdx.x;
    if (i < NN) { g_deg[i] = 0; g_cursor[i] = 0; }
}

__global__ void k_count(const int* __restrict__ dst) {
    int e = blockIdx.x * blockDim.x + threadIdx.x;
    if (e < NE) atomicAdd(&g_deg[dst[e]], 1);
}

__global__ void k_scan_tiles() {
    __shared__ int sh[1024];
    int t = threadIdx.x;
    int i = blockIdx.x * 1024 + t;
    int v = (i < NN) ? g_deg[i] : 0;
    sh[t] = v;
    __syncthreads();
    for (int d = 1; d < 1024; d <<= 1) {
        int x = 0;
        if (t >= d) x = sh[t - d];
        __syncthreads();
        sh[t] += x;
        __syncthreads();
    }
    if (i < NN) g_off[i] = sh[t] - v;
    if (t == 1023) g_tsum[blockIdx.x] = sh[t];
}

__global__ void k_scan_sums(int ntiles) {
    __shared__ int sh[64];
    int t = threadIdx.x;
    int v = (t < ntiles) ? g_tsum[t] : 0;
    sh[t] = v;
    __syncthreads();
    for (int d = 1; d < 64; d <<= 1) {
        int x = 0;
        if (t >= d) x = sh[t - d];
        __syncthreads();
        sh[t] += x;
        __syncthreads();
    }
    if (t < ntiles) g_tsum[t] = sh[t] - v;
}

__global__ void k_scan_fix() {
    int i = blockIdx.x * blockDim.x + threadIdx.x;
    if (i < NN) {
        g_off[i] += g_tsum[i >> 10];
        int d = g_deg[i];
        g_invdeg[i] = 1.0f / fmaxf((float)d, 1.0f);
        g_e1[i] = (d > 0) ? 1.0f : 0.0f;
    }
    if (i == 0) g_off[NN] = NE;
}

__global__ void k_fill(const int* __restrict__ src, const int* __restrict__ dst) {
    int e = blockIdx.x * blockDim.x + threadIdx.x;
    if (e < NE) {
        int d = dst[e];
        int pos = g_off[d] + atomicAdd(&g_cursor[d], 1);
        g_csr[pos] = src[e];
    }
}

// ---------------- fused precompute stages ----------------
// Stage A: Us = W2s@Wfc, Un = W2n@Wfc   (2 x 256x64 outputs, one kernel)
__global__ void k_preA(const float* __restrict__ W2s, const float* __restrict__ W2n,
                       const float* __restrict__ Wfc) {
    int idx = blockIdx.x * blockDim.x + threadIdx.x;
    if (idx >= 2 * 16384) return;
    int which = idx >> 14;
    int j = idx & 16383;
    int r = j >> 6, c = j & 63;
    const float* A = which ? W2n : W2s;
    float acc = 0.f;
    #pragma unroll 8
    for (int k = 0; k < 256; ++k) acc += A[r * 256 + k] * Wfc[k * 64 + c];
    g_pre[which * 16384 + j] = acc;
}

// Stage B: Q0 = W1s@Us ; Q1 = W1n@Us + W1s@Un ; Q2 = W1n@Un
__global__ void k_preB(const float* __restrict__ W1s, const float* __restrict__ W1n) {
    int idx = blockIdx.x * blockDim.x + threadIdx.x;
    if (idx >= 3 * 16384) return;
    int which = idx / 16384;
    int j = idx % 16384;
    int r = j >> 6, c = j & 63;
    const float* Us = g_pre;
    const float* Un = g_pre + 16384;
    float acc = 0.f;
    if (which == 0) {
        #pragma unroll 8
        for (int k = 0; k < 256; ++k) acc += W1s[r * 256 + k] * Us[k * 64 + c];
    } else if (which == 1) {
        #pragma unroll 8
        for (int k = 0; k < 256; ++k)
            acc += W1n[r * 256 + k] * Us[k * 64 + c] + W1s[r * 256 + k] * Un[k * 64 + c];
    } else {
        #pragma unroll 8
        for (int k = 0; k < 256; ++k) acc += W1n[r * 256 + k] * Un[k * 64 + c];
    }
    g_pre[32768 + which * 16384 + j] = acc;
}

// Stage C: 4 chunks of Cbig^T as bf16 hi/lo.
// chunk0 = W0s@Q0; chunk1 = W0n@Q0 + W0s@Q1; chunk2 = W0n@Q1 + W0s@Q2; chunk3 = W0n@Q2
__global__ void k_preC(const float* __restrict__ W0s, const float* __restrict__ W0n) {
    int idx = blockIdx.x * blockDim.x + threadIdx.x;
    if (idx >= 4 * 8192) return;
    int chunk = idx >> 13;
    int j = idx & 8191;
    int r = j >> 6, c = j & 63;          // r = k-index 0..127, c = n-local
    const float* Q0 = g_pre + 32768;
    const float* Q1 = g_pre + 49152;
    const float* Q2 = g_pre + 65536;
    float acc = 0.f;
    if (chunk == 0) {
        #pragma unroll 8
        for (int k = 0; k < 256; ++k) acc += W0s[r * 256 + k] * Q0[k * 64 + c];
    } else if (chunk == 1) {
        #pragma unroll 8
        for (int k = 0; k < 256; ++k)
            acc += W0n[r * 256 + k] * Q0[k * 64 + c] + W0s[r * 256 + k] * Q1[k * 64 + c];
    } else if (chunk == 2) {
        #pragma unroll 8
        for (int k = 0; k < 256; ++k)
            acc += W0n[r * 256 + k] * Q1[k * 64 + c] + W0s[r * 256 + k] * Q2[k * 64 + c];
    } else {
        #pragma unroll 8
        for (int k = 0; k < 256; ++k) acc += W0n[r * 256 + k] * Q2[k * 64 + c];
    }
    __nv_bfloat16 h = __float2bfloat16(acc);
    g_CTh[chunk * 8192 + c * 128 + r] = h;
    g_CTl[chunk * 8192 + c * 128 + r] = __float2bfloat16(acc - __bfloat162float(h));
}

// r0 = b0@Q0 + b1@Us + b2@Wfc + bfc ; r1 = b0@Q1 + b1@Un ; r2 = b0@Q2
__global__ void k_rvec(const float* __restrict__ b0, const float* __restrict__ b1,
                       const float* __restrict__ b2, const float* __restrict__ bfc,
                       const float* __restrict__ Wfc) {
    const float* Us = g_pre;
    const float* Un = g_pre + 16384;
    const float* Q0 = g_pre + 32768;
    const float* Q1 = g_pre + 49152;
    const float* Q2 = g_pre + 65536;
    int t = threadIdx.x;
    int which = t / 64, c = t % 64;
    float acc = 0.f;
    if (which == 0) {
        for (int k = 0; k < 256; ++k)
            acc += b0[k] * Q0[k * 64 + c] + b1[k] * Us[k * 64 + c] + b2[k] * Wfc[k * 64 + c];
        acc += bfc[c];
    } else if (which == 1) {
        for (int k = 0; k < 256; ++k)
            acc += b0[k] * Q1[k * 64 + c] + b1[k] * Un[k * 64 + c];
    } else {
        for (int k = 0; k < 256; ++k)
            acc += b0[k] * Q2[k * 64 + c];
    }
    g_r[t] = acc;
}

// ---------------- 64-dim mean gather, x4 unrolled, fused add ----------------
// mode: 0 = plain ; 1 = also compute g_e2 (lane c==0) ; 2 = add bias combo
__global__ void k_gather64(const float4* __restrict__ src, int lds,
                           const float4* __restrict__ add, int lda,
                           float4* __restrict__ out, int ldo, int mode) {
    int gtid = blockIdx.x * blockDim.x + threadIdx.x;
    int node = gtid >> 4;
    int c = gtid & 15;
    if (node >= NN) return;
    int s = g_off[node], e = g_off[node + 1];
    float4 acc0 = make_float4(0.f, 0.f, 0.f, 0.f);
    float4 acc1 = make_float4(0.f, 0.f, 0.f, 0.f);
    float ecnt = 0.f;
    int idx = s;
    for (; idx + 4 <= e; idx += 4) {
        int n0 = g_csr[idx],     n1 = g_csr[idx + 1];
        int n2 = g_csr[idx + 2], n3 = g_csr[idx + 3];
        float4 v0 = src[(size_t)n0 * lds + c];
        float4 v1 = src[(size_t)n1 * lds + c];
        float4 v2 = src[(size_t)n2 * lds + c];
        float4 v3 = src[(size_t)n3 * lds + c];
        if (mode == 1 && c == 0)
            ecnt += ((g_deg[n0] > 0) ? 1.f : 0.f) + ((g_deg[n1] > 0) ? 1.f : 0.f)
                  + ((g_deg[n2] > 0) ? 1.f : 0.f) + ((g_deg[n3] > 0) ? 1.f : 0.f);
        acc0.x += v0.x; acc0.y += v0.y; acc0.z += v0.z; acc0.w += v0.w;
        acc1.x += v1.x; acc1.y += v1.y; acc1.z += v1.z; acc1.w += v1.w;
        acc0.x += v2.x; acc0.y += v2.y; acc0.z += v2.z; acc0.w += v2.w;
        acc1.x += v3.x; acc1.y += v3.y; acc1.z += v3.z; acc1.w += v3.w;
    }
    for (; idx < e; ++idx) {
        int sn = g_csr[idx];
        float4 v = src[(size_t)sn * lds + c];
        if (mode == 1 && c == 0) ecnt += (g_deg[sn] > 0) ? 1.f : 0.f;
        acc0.x += v.x; acc0.y += v.y; acc0.z += v.z; acc0.w += v.w;
    }
    acc0.x += acc1.x; acc0.y += acc1.y; acc0.z += acc1.z; acc0.w += acc1.w;
    float w = g_invdeg[node];
    if (mode == 1 && c == 0) g_e2[node] = ecnt * w;
    float4 r = add[(size_t)node * lda + c];
    r.x += acc0.x * w; r.y += acc0.y * w; r.z += acc0.z * w; r.w += acc0.w * w;
    if (mode == 2) {
        float a = g_e1[node], b = g_e2[node];
        const float4* r0 = (const float4*)g_r;
        const float4* r1 = r0 + 16;
        const float4* r2 = r0 + 32;
        float4 v0 = r0[c], v1 = r1[c], v2 = r2[c];
        r.x += v0.x + a * v1.x + b * v2.x;
        r.y += v0.y + a * v1.y + b * v2.y;
        r.z += v0.z + a * v1.z + b * v2.z;
        r.w += v0.w + a * v1.w + b * v2.w;
    }
    out[(size_t)node * ldo + c] = r;
}

// ---------------- mma.sync bf16 split-precision GEMM (unchanged, proven) ----------------
#define LDK 136
#define SM_AH 0
#define SM_AL (128 * LDK)
#define SM_BH (2 * 128 * LDK)
#define SM_BL (3 * 128 * LDK)
#define SM_HALVES (4 * 128 * LDK)

#define MMA16816(c, a, b0_, b1_) \
    asm volatile("mma.sync.aligned.m16n8k16.row.col.f32.bf16.bf16.f32 " \
        "{%0,%1,%2,%3}, {%4,%5,%6,%7}, {%8,%9}, {%0,%1,%2,%3};" \
        : "+f"((c)[0]), "+f"((c)[1]), "+f"((c)[2]), "+f"((c)[3]) \
        : "r"((a)[0]), "r"((a)[1]), "r"((a)[2]), "r"((a)[3]), \
          "r"(b0_), "r"(b1_))

__global__ __launch_bounds__(256, 1)
void k_wgemm(const float* __restrict__ x, const __nv_bfloat16* __restrict__ CTh,
             const __nv_bfloat16* __restrict__ CTl, float* __restrict__ U, int M) {
    extern __shared__ __nv_bfloat16 sm[];
    __nv_bfloat16* Ah = sm + SM_AH;
    __nv_bfloat16* Al = sm + SM_AL;
    __nv_bfloat16* Bh = sm + SM_BH;
    __nv_bfloat16* Bl = sm + SM_BL;

    const int tid = threadIdx.x;
    const int bm = blockIdx.y * 128;
    const int bn = blockIdx.x * 128;

    {
        int r = tid >> 1;
        int half = tid & 1;
        int grow = bm + r;
        const float4* xr = (const float4*)(x + (size_t)grow * 128 + half * 64);
        __nv_bfloat16* ah = Ah + r * LDK + half * 64;
        __nv_bfloat16* al = Al + r * LDK + half * 64;
        #pragma unroll
        for (int j = 0; j < 8; ++j) {
            float f[8];
            if (grow < M) {
                float4 v0 = xr[2 * j], v1 = xr[2 * j + 1];
                f[0] = v0.x; f[1] = v0.y; f[2] = v0.z; f[3] = v0.w;
                f[4] = v1.x; f[5] = v1.y; f[6] = v1.z; f[7] = v1.w;
            } else {
                #pragma unroll
                for (int e = 0; e < 8; ++e) f[e] = 0.f;
            }
            uint32_t hp[4], lp[4];
            #pragma unroll
            for (int e = 0; e < 4; ++e) {
                __nv_bfloat16 h0 = __float2bfloat16(f[2 * e]);
                __nv_bfloat16 h1 = __float2bfloat16(f[2 * e + 1]);
                float l0 = f[2 * e]     - __bfloat162float(h0);
                float l1 = f[2 * e + 1] - __bfloat162float(h1);
                __nv_bfloat162 hh = __halves2bfloat162(h0, h1);
                __nv_bfloat162 lv = __halves2bfloat162(__float2bfloat16(l0),
                                                       __float2bfloat16(l1));
                hp[e] = *(uint32_t*)&hh;
                lp[e] = *(uint32_t*)&lv;
            }
            *(uint4*)(ah + 8 * j) = make_uint4(hp[0], hp[1], hp[2], hp[3]);
            *(uint4*)(al + 8 * j) = make_uint4(lp[0], lp[1], lp[2], lp[3]);
        }
    }
    {
        int r = tid >> 1;
        int half = tid & 1;
        const uint4* sh = (const uint4*)(CTh + (size_t)(bn + r) * 128 + half * 64);
        const uint4* sl = (const uint4*)(CTl + (size_t)(bn + r) * 128 + half * 64);
        uint4* dh = (uint4*)(Bh + r * LDK + half * 64);
        uint4* dl = (uint4*)(Bl + r * LDK + half * 64);
        #pragma unroll
        for (int j = 0; j < 8; ++j) { dh[j] = sh[j]; dl[j] = sl[j]; }
    }
    __syncthreads();

    const int w = tid >> 5, lane = tid & 31;
    const int wm = (w >> 2) * 64;
    const int wn = (w & 3) * 32;
    const int lr = lane >> 2;
    const int lc = (lane & 3) * 2;

    float acc[4][4][4];
    #pragma unroll
    for (int i = 0; i < 4; ++i)
        #pragma unroll
        for (int j = 0; j < 4; ++j)
            #pragma unroll
            for (int e = 0; e < 4; ++e) acc[i][j][e] = 0.f;

    #pragma unroll
    for (int pass = 0; pass < 3; ++pass) {
        const __nv_bfloat16* As = (pass == 2) ? Al : Ah;
        const __nv_bfloat16* Bs = (pass == 1) ? Bl : Bh;
        #pragma unroll
        for (int ks = 0; ks < 8; ++ks) {
            int kb = ks * 16;
            uint32_t a[4][4];
            #pragma unroll
            for (int fm = 0; fm < 4; ++fm) {
                int r = wm + fm * 16 + lr;
                a[fm][0] = *(const uint32_t*)&As[r * LDK + kb + lc];
                a[fm][1] = *(const uint32_t*)&As[(r + 8) * LDK + kb + lc];
                a[fm][2] = *(const uint32_t*)&As[r * LDK + kb + 8 + lc];
                a[fm][3] = *(const uint32_t*)&As[(r + 8) * LDK + kb + 8 + lc];
            }
            #pragma unroll
            for (int fn = 0; fn < 4; ++fn) {
                int n = wn + fn * 8 + lr;
                uint32_t b0 = *(const uint32_t*)&Bs[n * LDK + kb + lc];
                uint32_t b1 = *(const uint32_t*)&Bs[n * LDK + kb + 8 + lc];
                #pragma unroll
                for (int fm = 0; fm < 4; ++fm)
                    MMA16816(acc[fm][fn], a[fm], b0, b1);
            }
        }
    }

    #pragma unroll
    for (int fm = 0; fm < 4; ++fm) {
        int r0 = bm + wm + fm * 16 + lr;
        int r1 = r0 + 8;
        #pragma unroll
        for (int fn = 0; fn < 4; ++fn) {
            int col = bn + wn + fn * 8 + lc;
            if (r0 < M)
                *(float2*)(U + (size_t)r0 * 256 + col) =
                    make_float2(acc[fm][fn][0], acc[fm][fn][1]);
            if (r1 < M)
                *(float2*)(U + (size_t)r1 * 256 + col) =
                    make_float2(acc[fm][fn][2], acc[fm][fn][3]);
        }
    }
}

// ---------------- launch ----------------
extern "C" void kernel_launch(void* const* d_in, const int* in_sizes, int n_in,
                              void* d_out, int out_size) {
    const float* x    = (const float*)d_in[0];
    const int*   esrc = (const int*)d_in[1];
    const int*   edst = (const int*)d_in[2];
    const float* W0s  = (const float*)d_in[3];
    const float* W0n  = (const float*)d_in[4];
    const float* b0   = (const float*)d_in[5];
    const float* W1s  = (const float*)d_in[6];
    const float* W1n  = (const float*)d_in[7];
    const float* b1   = (const float*)d_in[8];
    const float* W2s  = (const float*)d_in[9];
    const float* W2n  = (const float*)d_in[10];
    const float* b2   = (const float*)d_in[11];
    const float* Wfc  = (const float*)d_in[12];
    const float* bfc  = (const float*)d_in[13];
    float* out = (float*)d_out;

    float *U, *sbuf;
    __nv_bfloat16 *CTh, *CTl;
    cudaGetSymbolAddress((void**)&U,    g_U);
    cudaGetSymbolAddress((void**)&sbuf, g_s);
    cudaGetSymbolAddress((void**)&CTh,  g_CTh);
    cudaGetSymbolAddress((void**)&CTl,  g_CTl);

    const int TB = 256;
    int nblk_n = (NN + TB - 1) / TB;
    int nblk_e = (NE + TB - 1) / TB;
    int ntiles = (NN + 1023) / 1024;

    // ---- CSR build ----
    k_zero_counts<<<nblk_n, TB>>>();
    k_count<<<nblk_e, TB>>>(edst);
    k_scan_tiles<<<ntiles, 1024>>>();
    k_scan_sums<<<1, 64>>>(ntiles);
    k_scan_fix<<<nblk_n, TB>>>();
    k_fill<<<nblk_e, TB>>>(esrc, edst);

    // ---- fused weight precompute (3 kernels + rvec) ----
    k_preA<<<(2 * 16384 + TB - 1) / TB, TB>>>(W2s, W2n, Wfc);
    k_preB<<<(3 * 16384 + TB - 1) / TB, TB>>>(W1s, W1n);
    k_preC<<<(4 * 8192 + TB - 1) / TB, TB>>>(W0s, W0n);
    k_rvec<<<1, 192>>>(b0, b1, b2, bfc, Wfc);

    // ---- main GEMM on mma.sync tensor path ----
    size_t smem_bytes = (size_t)SM_HALVES * sizeof(__nv_bfloat16);
    cudaFuncSetAttribute(k_wgemm, cudaFuncAttributeMaxDynamicSharedMemorySize,
                         (int)smem_bytes);
    dim3 gG(2, (NN + 127) / 128);
    k_wgemm<<<gG, 256, smem_bytes>>>(x, CTh, CTl, U, NN);

    // ---- Horner aggregation: out = u0 + S(u1 + S(u2 + S(u3))) + bias ----
    const float4* Uf = (const float4*)U;
    float4* s2 = (float4*)sbuf;
    float4* s1 = (float4*)(sbuf + (size_t)NN * 64);
    int gblk = (NN * 16 + TB - 1) / TB;
    k_gather64<<<gblk, TB>>>(Uf + 48, 64, Uf + 32, 64, s2, 16, 1);
    k_gather64<<<gblk, TB>>>(s2, 16, Uf + 16, 64, s1, 16, 0);
    k_gather64<<<gblk, TB>>>(s1, 16, Uf + 0, 64, (float4*)out, 16, 2);
}